// round 2
// baseline (speedup 1.0000x reference)
#include <cuda_runtime.h>
#include <cuda_bf16.h>
#include <math.h>

#define NBINS 128
#define NFREQ 64
#define NKERN 3
#define MLPH  64
#define KPB   16   // keys per block
#define TPB   256  // two half-blocks of 128; each half handles 8 keys

// Precomputed per-(f,m,b) coefficients: {kappa*log2e*cos(mu_eff), kappa*log2e*sin(mu_eff), -kappa*log2e, weight}
// Layout [f][m][b] so per-bin threads load coalesced float4s.
__device__ float4 g_coef[NFREQ * NKERN * NBINS];

__global__ void precompute_coef(const float* __restrict__ mu,
                                const float* __restrict__ kappa,
                                const float* __restrict__ weight,
                                const float* __restrict__ ref_angles) {
    int idx = blockIdx.x * blockDim.x + threadIdx.x;
    if (idx >= NBINS * NFREQ * NKERN) return;
    int b = idx / (NFREQ * NKERN);
    int f = (idx / NKERN) % NFREQ;
    int m = idx % NKERN;
    float me = mu[idx] + ref_angles[f];
    const float L2E = 1.4426950408889634f;
    float kl = kappa[idx] * L2E;
    float sn, cs;
    sincosf(me, &sn, &cs);
    g_coef[(f * NKERN + m) * NBINS + b] = make_float4(kl * cs, kl * sn, -kl, weight[idx]);
}

__global__ __launch_bounds__(TPB)
void key_pruning_main(const float2* __restrict__ K2,      // [N*64] (x,y) pairs
                      const int*    __restrict__ pos,
                      const float*  __restrict__ bias,
                      const float*  __restrict__ W1,      // [64][128]
                      const float*  __restrict__ b1,      // [64]
                      const float*  __restrict__ W2,      // [64]
                      const float*  __restrict__ b2,      // [1]
                      const float*  __restrict__ araw,    // [3]
                      float*        __restrict__ out,
                      int n) {
    __shared__ float sl[KPB * NBINS];   // logits [kk][b]
    __shared__ union {
        struct { float c[NFREQ * KPB]; float s[NFREQ * KPB]; float m[NFREQ * KPB]; } trig;
        struct { float w1[MLPH * 129]; float h[KPB * MLPH]; float b1w2[2 * MLPH]; } mlp;
    } u;

    const int tid  = threadIdx.x;
    const int bin  = tid & (NBINS - 1);      // bin index
    const int half = tid >> 7;               // 0: keys 0-7, 1: keys 8-15
    const int key0 = blockIdx.x * KPB;

    // ---- Phase 1: per-key trig via identity (cosA = x/r, sinA = y/r, mag = r) ----
    for (int i = tid; i < KPB * NFREQ; i += TPB) {
        int kk = i >> 6;
        int f  = i & 63;
        int key = key0 + kk; if (key >= n) key = n - 1;
        float2 v = K2[key * NFREQ + f];
        float r2 = fmaf(v.x, v.x, v.y * v.y);
        r2 = fmaxf(r2, 1e-30f);
        float rinv = rsqrtf(r2);
        u.trig.c[f * KPB + kk] = v.x * rinv;
        u.trig.s[f * KPB + kk] = v.y * rinv;
        u.trig.m[f * KPB + kk] = r2 * rinv;
    }
    __syncthreads();

    // ---- Phase 2: von Mises accumulation. Thread = (bin, key-half). EX2-bound. ----
    float acc[8];
    #pragma unroll
    for (int j = 0; j < 8; j++) acc[j] = 0.f;

    const int kbase = half * 8;
    const float4* cptr = g_coef + bin;
    for (int f = 0; f < NFREQ; f++) {
        float4 c0 = cptr[(f * 3 + 0) * NBINS];
        float4 c1 = cptr[(f * 3 + 1) * NBINS];
        float4 c2 = cptr[(f * 3 + 2) * NBINS];
        #pragma unroll
        for (int j = 0; j < 8; j++) {
            int kk = kbase + j;
            float cA = u.trig.c[f * KPB + kk];   // broadcast LDS within warp
            float sA = u.trig.s[f * KPB + kk];
            float mg = u.trig.m[f * KPB + kk];
            float e0 = exp2f(fmaf(c0.x, cA, fmaf(c0.y, sA, c0.z)));
            float e1 = exp2f(fmaf(c1.x, cA, fmaf(c1.y, sA, c1.z)));
            float e2 = exp2f(fmaf(c2.x, cA, fmaf(c2.y, sA, c2.z)));
            float inner = fmaf(c0.w, e0, fmaf(c1.w, e1, c2.w * e2));
            acc[j] = fmaf(mg, inner, acc[j]);
        }
    }

    float bb = bias[bin];
    #pragma unroll
    for (int j = 0; j < 8; j++) sl[(kbase + j) * NBINS + bin] = acc[j] + bb;
    __syncthreads();   // trig region dead from here; union flips to MLP use

    // ---- Phase 3: stage W1 (padded stride 129 -> conflict-free), b1, W2 ----
    for (int i = tid; i < MLPH * NBINS; i += TPB)
        u.mlp.w1[(i >> 7) * 129 + (i & 127)] = W1[i];
    if (tid < MLPH) {
        u.mlp.b1w2[tid]        = b1[tid];
        u.mlp.b1w2[MLPH + tid] = W2[tid];
    }
    __syncthreads();

    // ---- Phase 4: layer 1 (relu) with W2 folded in. 1024 tasks / 256 thr ----
    #pragma unroll
    for (int t = 0; t < KPB * MLPH; t += TPB) {
        int task = t + tid;
        int kk = task >> 6;
        int j  = task & 63;
        float a = u.mlp.b1w2[j];
        const float* lr = &sl[kk * NBINS];
        const float* wr = &u.mlp.w1[j * 129];
        #pragma unroll 16
        for (int b = 0; b < NBINS; b++) a = fmaf(lr[b], wr[b], a);
        a = fmaxf(a, 0.f);
        u.mlp.h[kk * MLPH + j] = a * u.mlp.b1w2[MLPH + j];
    }
    __syncthreads();

    // ---- Phase 5: reduce, position weight, sigmoid ----
    if (tid < KPB && (key0 + tid) < n) {
        float s = b2[0];
        #pragma unroll 16
        for (int j = 0; j < MLPH; j++) s += u.mlp.h[tid * MLPH + j];

        int p = pos[key0 + tid];
        float lp = log10f(fmaxf((float)p, 1.0f));
        float a0 = log1pf(expf(araw[0]));
        float a1 = log1pf(expf(araw[1]));
        float a2 = log1pf(expf(araw[2]));
        float w;
        if (lp < 3.f)      w = a0;
        else if (lp < 4.f) w = a0 + (a1 - a0) * (lp - 3.f);
        else if (lp < 5.f) w = a1 + (a2 - a1) * (lp - 4.f);
        else               w = a2;

        float z = s * w;
        out[key0 + tid] = 1.f / (1.f + expf(-z));
    }
}

extern "C" void kernel_launch(void* const* d_in, const int* in_sizes, int n_in,
                              void* d_out, int out_size) {
    const float* K      = (const float*)d_in[0];
    const int*   pos    = (const int*)  d_in[1];
    const float* ra     = (const float*)d_in[2];
    const float* mu     = (const float*)d_in[3];
    const float* kappa  = (const float*)d_in[4];
    const float* weight = (const float*)d_in[5];
    const float* bias   = (const float*)d_in[6];
    const float* W1     = (const float*)d_in[7];
    const float* b1     = (const float*)d_in[8];
    const float* W2     = (const float*)d_in[9];
    const float* b2     = (const float*)d_in[10];
    const float* araw   = (const float*)d_in[11];

    int n = in_sizes[1];   // number of keys (key_positions length)

    precompute_coef<<<(NBINS * NFREQ * NKERN + 255) / 256, 256>>>(mu, kappa, weight, ra);

    int grid = (n + KPB - 1) / KPB;
    key_pruning_main<<<grid, TPB>>>((const float2*)K, pos, bias, W1, b1, W2, b2, araw,
                                    (float*)d_out, n);
}

// round 3
// speedup vs baseline: 1.2127x; 1.2127x over previous
#include <cuda_runtime.h>
#include <cuda_bf16.h>
#include <math.h>

#define NBINS 128
#define NFREQ 64
#define NKERN 3
#define MLPH  64
#define KPB   16   // keys per block
#define TPB   256  // two half-blocks of 128; each half handles 8 keys

__device__ __forceinline__ float ex2_fast(float x) {
    float y;
    asm("ex2.approx.ftz.f32 %0, %1;" : "=f"(y) : "f"(x));
    return y;
}

// Precomputed per-(f,m,b) coefficients: {kappa*log2e*cos(mu_eff), kappa*log2e*sin(mu_eff), -kappa*log2e, weight}
__device__ float4 g_coef[NFREQ * NKERN * NBINS];

__global__ void precompute_coef(const float* __restrict__ mu,
                                const float* __restrict__ kappa,
                                const float* __restrict__ weight,
                                const float* __restrict__ ref_angles) {
    int idx = blockIdx.x * blockDim.x + threadIdx.x;
    if (idx >= NBINS * NFREQ * NKERN) return;
    int b = idx / (NFREQ * NKERN);
    int f = (idx / NKERN) % NFREQ;
    int m = idx % NKERN;
    float me = mu[idx] + ref_angles[f];
    const float L2E = 1.4426950408889634f;
    float kl = kappa[idx] * L2E;
    float sn, cs;
    sincosf(me, &sn, &cs);
    g_coef[(f * NKERN + m) * NBINS + b] = make_float4(kl * cs, kl * sn, -kl, weight[idx]);
}

__global__ __launch_bounds__(TPB)
void key_pruning_main(const float2* __restrict__ K2,      // [N*64] (x,y) pairs
                      const int*    __restrict__ pos,
                      const float*  __restrict__ bias,
                      const float*  __restrict__ W1,      // [64][128]
                      const float*  __restrict__ b1,      // [64]
                      const float*  __restrict__ W2,      // [64]
                      const float*  __restrict__ b2,      // [1]
                      const float*  __restrict__ araw,    // [3]
                      float*        __restrict__ out,
                      int n) {
    __shared__ float sl[KPB * NBINS];   // logits [kk][b]
    __shared__ union {
        struct { float c[NFREQ * KPB]; float s[NFREQ * KPB]; float m[NFREQ * KPB]; } trig;
        struct { float w1[MLPH * 129]; float h[KPB * MLPH]; float b1w2[2 * MLPH]; } mlp;
    } u;

    const int tid  = threadIdx.x;
    const int bin  = tid & (NBINS - 1);      // bin index
    const int half = tid >> 7;               // 0: keys 0-7, 1: keys 8-15
    const int key0 = blockIdx.x * KPB;

    // ---- Phase 1: per-key trig via identity (cosA = x/r, sinA = y/r, mag = r) ----
    for (int i = tid; i < KPB * NFREQ; i += TPB) {
        int kk = i >> 6;
        int f  = i & 63;
        int key = key0 + kk; if (key >= n) key = n - 1;
        float2 v = K2[key * NFREQ + f];
        float r2 = fmaf(v.x, v.x, v.y * v.y);
        r2 = fmaxf(r2, 1e-30f);
        float rinv = rsqrtf(r2);
        u.trig.c[f * KPB + kk] = v.x * rinv;
        u.trig.s[f * KPB + kk] = v.y * rinv;
        u.trig.m[f * KPB + kk] = r2 * rinv;
    }
    __syncthreads();

    // ---- Phase 2: von Mises accumulation. Thread = (bin, key-half). MUFU.EX2-bound. ----
    float acc[8];
    #pragma unroll
    for (int j = 0; j < 8; j++) acc[j] = 0.f;

    const int kbase = half * 8;
    const float4* cptr = g_coef + bin;
    for (int f = 0; f < NFREQ; f++) {
        float4 c0 = cptr[(f * 3 + 0) * NBINS];
        float4 c1 = cptr[(f * 3 + 1) * NBINS];
        float4 c2 = cptr[(f * 3 + 2) * NBINS];
        #pragma unroll
        for (int j = 0; j < 8; j++) {
            int kk = kbase + j;
            float cA = u.trig.c[f * KPB + kk];   // broadcast LDS within warp
            float sA = u.trig.s[f * KPB + kk];
            float mg = u.trig.m[f * KPB + kk];
            float e0 = ex2_fast(fmaf(c0.x, cA, fmaf(c0.y, sA, c0.z)));
            float e1 = ex2_fast(fmaf(c1.x, cA, fmaf(c1.y, sA, c1.z)));
            float e2 = ex2_fast(fmaf(c2.x, cA, fmaf(c2.y, sA, c2.z)));
            float inner = fmaf(c0.w, e0, fmaf(c1.w, e1, c2.w * e2));
            acc[j] = fmaf(mg, inner, acc[j]);
        }
    }

    float bb = bias[bin];
    #pragma unroll
    for (int j = 0; j < 8; j++) sl[(kbase + j) * NBINS + bin] = acc[j] + bb;
    __syncthreads();   // trig region dead from here; union flips to MLP use

    // ---- Phase 3: stage W1 (padded stride 129 -> conflict-free), b1, W2 ----
    for (int i = tid; i < MLPH * NBINS; i += TPB)
        u.mlp.w1[(i >> 7) * 129 + (i & 127)] = W1[i];
    if (tid < MLPH) {
        u.mlp.b1w2[tid]        = b1[tid];
        u.mlp.b1w2[MLPH + tid] = W2[tid];
    }
    __syncthreads();

    // ---- Phase 4: layer 1 (relu) with W2 folded in. 1024 tasks / 256 thr ----
    #pragma unroll
    for (int t = 0; t < KPB * MLPH; t += TPB) {
        int task = t + tid;
        int kk = task >> 6;
        int j  = task & 63;
        float a = u.mlp.b1w2[j];
        const float* lr = &sl[kk * NBINS];
        const float* wr = &u.mlp.w1[j * 129];
        #pragma unroll 16
        for (int b = 0; b < NBINS; b++) a = fmaf(lr[b], wr[b], a);
        a = fmaxf(a, 0.f);
        u.mlp.h[kk * MLPH + j] = a * u.mlp.b1w2[MLPH + j];
    }
    __syncthreads();

    // ---- Phase 5: reduce, position weight, sigmoid ----
    if (tid < KPB && (key0 + tid) < n) {
        float s = b2[0];
        #pragma unroll 16
        for (int j = 0; j < MLPH; j++) s += u.mlp.h[tid * MLPH + j];

        int p = pos[key0 + tid];
        float lp = log10f(fmaxf((float)p, 1.0f));
        float a0 = log1pf(expf(araw[0]));
        float a1 = log1pf(expf(araw[1]));
        float a2 = log1pf(expf(araw[2]));
        float w;
        if (lp < 3.f)      w = a0;
        else if (lp < 4.f) w = a0 + (a1 - a0) * (lp - 3.f);
        else if (lp < 5.f) w = a1 + (a2 - a1) * (lp - 4.f);
        else               w = a2;

        float z = s * w;
        out[key0 + tid] = 1.f / (1.f + expf(-z));
    }
}

extern "C" void kernel_launch(void* const* d_in, const int* in_sizes, int n_in,
                              void* d_out, int out_size) {
    const float* K      = (const float*)d_in[0];
    const int*   pos    = (const int*)  d_in[1];
    const float* ra     = (const float*)d_in[2];
    const float* mu     = (const float*)d_in[3];
    const float* kappa  = (const float*)d_in[4];
    const float* weight = (const float*)d_in[5];
    const float* bias   = (const float*)d_in[6];
    const float* W1     = (const float*)d_in[7];
    const float* b1     = (const float*)d_in[8];
    const float* W2     = (const float*)d_in[9];
    const float* b2     = (const float*)d_in[10];
    const float* araw   = (const float*)d_in[11];

    int n = in_sizes[1];   // number of keys (key_positions length)

    precompute_coef<<<(NBINS * NFREQ * NKERN + 255) / 256, 256>>>(mu, kappa, weight, ra);

    int grid = (n + KPB - 1) / KPB;
    key_pruning_main<<<grid, TPB>>>((const float2*)K, pos, bias, W1, b1, W2, b2, araw,
                                    (float*)d_out, n);
}

// round 4
// speedup vs baseline: 1.3435x; 1.1079x over previous
#include <cuda_runtime.h>
#include <cuda_bf16.h>
#include <math.h>

#define NBINS 128
#define NFREQ 64
#define NKERN 3
#define MLPH  64
#define KPB   28   // keys per block -> grid 293 <= 2*148, near-perfect single-wave balance
#define TPB   512  // 4 quarters of 128 bins; each quarter handles 7 keys

__device__ __forceinline__ float ex2_fast(float x) {
    float y;
    asm("ex2.approx.ftz.f32 %0, %1;" : "=f"(y) : "f"(x));
    return y;
}

// Precomputed per-(f,m,b) coefficients: {k*log2e*cos(mu_eff), k*log2e*sin(mu_eff), -k*log2e, weight}
__device__ float4 g_coef[NFREQ * NKERN * NBINS];

__global__ void precompute_coef(const float* __restrict__ mu,
                                const float* __restrict__ kappa,
                                const float* __restrict__ weight,
                                const float* __restrict__ ref_angles) {
    int idx = blockIdx.x * blockDim.x + threadIdx.x;
    if (idx >= NBINS * NFREQ * NKERN) return;
    int b = idx / (NFREQ * NKERN);
    int f = (idx / NKERN) % NFREQ;
    int m = idx % NKERN;
    float me = mu[idx] + ref_angles[f];
    const float L2E = 1.4426950408889634f;
    float kl = kappa[idx] * L2E;
    float sn, cs;
    sincosf(me, &sn, &cs);
    g_coef[(f * NKERN + m) * NBINS + b] = make_float4(kl * cs, kl * sn, -kl, weight[idx]);
}

__global__ __launch_bounds__(TPB, 2)
void key_pruning_main(const float2* __restrict__ K2,      // [N*64] (x,y) pairs
                      const int*    __restrict__ pos,
                      const float*  __restrict__ bias,
                      const float*  __restrict__ W1,      // [64][128]
                      const float*  __restrict__ b1,      // [64]
                      const float*  __restrict__ W2,      // [64]
                      const float*  __restrict__ b2,      // [1]
                      const float*  __restrict__ araw,    // [3]
                      float*        __restrict__ out,
                      int n) {
    __shared__ float sl[KPB * NBINS];                     // logits [kk][b]  (14 KB)
    __shared__ union {
        float4 trig[NFREQ * KPB];                         // {cos,sin,mag,_} per (f,kk)  (28 KB)
        struct { float w1[MLPH * 129]; float h[KPB * MLPH]; float b1w2[2 * MLPH]; } mlp; // ~41 KB
    } u;

    const int tid  = threadIdx.x;
    const int bin  = tid & (NBINS - 1);
    const int quad = tid >> 7;               // 0..3 -> keys [7*quad, 7*quad+7)
    const int key0 = blockIdx.x * KPB;

    // ---- Phase 1: per-key trig via identity (cosA = x/r, sinA = y/r, mag = r) ----
    for (int i = tid; i < KPB * NFREQ; i += TPB) {
        int kk = i / NFREQ;
        int f  = i & 63;
        int key = key0 + kk; if (key >= n) key = n - 1;
        float2 v = K2[key * NFREQ + f];
        float r2 = fmaf(v.x, v.x, v.y * v.y);
        r2 = fmaxf(r2, 1e-30f);
        float rinv = rsqrtf(r2);
        u.trig[f * KPB + kk] = make_float4(v.x * rinv, v.y * rinv, r2 * rinv, 0.f);
    }
    __syncthreads();

    // ---- Phase 2: von Mises accumulation. Thread = (bin, quarter). MUFU.EX2-bound. ----
    float acc[7];
    #pragma unroll
    for (int j = 0; j < 7; j++) acc[j] = 0.f;

    const int kbase = quad * 7;
    const float4* cptr = g_coef + bin;
    #pragma unroll 2
    for (int f = 0; f < NFREQ; f++) {
        float4 c0 = cptr[(f * 3 + 0) * NBINS];
        float4 c1 = cptr[(f * 3 + 1) * NBINS];
        float4 c2 = cptr[(f * 3 + 2) * NBINS];
        #pragma unroll
        for (int j = 0; j < 7; j++) {
            float4 t = u.trig[f * KPB + kbase + j];   // single LDS.128 broadcast
            float e0 = ex2_fast(fmaf(c0.x, t.x, fmaf(c0.y, t.y, c0.z)));
            float e1 = ex2_fast(fmaf(c1.x, t.x, fmaf(c1.y, t.y, c1.z)));
            float e2 = ex2_fast(fmaf(c2.x, t.x, fmaf(c2.y, t.y, c2.z)));
            float inner = fmaf(c0.w, e0, fmaf(c1.w, e1, c2.w * e2));
            acc[j] = fmaf(t.z, inner, acc[j]);
        }
    }

    float bb = bias[bin];
    #pragma unroll
    for (int j = 0; j < 7; j++) sl[(kbase + j) * NBINS + bin] = acc[j] + bb;
    __syncthreads();   // trig region dead from here; union flips to MLP use

    // ---- Phase 3: stage W1 (padded stride 129 -> conflict-free), b1, W2 ----
    for (int i = tid; i < MLPH * NBINS; i += TPB)
        u.mlp.w1[(i >> 7) * 129 + (i & 127)] = W1[i];
    if (tid < MLPH) {
        u.mlp.b1w2[tid]        = b1[tid];
        u.mlp.b1w2[MLPH + tid] = W2[tid];
    }
    __syncthreads();

    // ---- Phase 4: layer 1 (relu) with W2 folded in. KPB*64 = 1792 tasks ----
    for (int t = 0; t < KPB * MLPH; t += TPB) {
        int task = t + tid;
        if (task < KPB * MLPH) {
            int kk = task >> 6;
            int j  = task & 63;
            float a = u.mlp.b1w2[j];
            const float* lr = &sl[kk * NBINS];
            const float* wr = &u.mlp.w1[j * 129];
            #pragma unroll 16
            for (int b = 0; b < NBINS; b++) a = fmaf(lr[b], wr[b], a);
            a = fmaxf(a, 0.f);
            u.mlp.h[kk * MLPH + j] = a * u.mlp.b1w2[MLPH + j];
        }
    }
    __syncthreads();

    // ---- Phase 5: reduce, position weight, sigmoid ----
    if (tid < KPB && (key0 + tid) < n) {
        float s = b2[0];
        #pragma unroll 16
        for (int j = 0; j < MLPH; j++) s += u.mlp.h[tid * MLPH + j];

        int p = pos[key0 + tid];
        float lp = log10f(fmaxf((float)p, 1.0f));
        float a0 = log1pf(expf(araw[0]));
        float a1 = log1pf(expf(araw[1]));
        float a2 = log1pf(expf(araw[2]));
        float w;
        if (lp < 3.f)      w = a0;
        else if (lp < 4.f) w = a0 + (a1 - a0) * (lp - 3.f);
        else if (lp < 5.f) w = a1 + (a2 - a1) * (lp - 4.f);
        else               w = a2;

        float z = s * w;
        out[key0 + tid] = 1.f / (1.f + expf(-z));
    }
}

extern "C" void kernel_launch(void* const* d_in, const int* in_sizes, int n_in,
                              void* d_out, int out_size) {
    const float* K      = (const float*)d_in[0];
    const int*   pos    = (const int*)  d_in[1];
    const float* ra     = (const float*)d_in[2];
    const float* mu     = (const float*)d_in[3];
    const float* kappa  = (const float*)d_in[4];
    const float* weight = (const float*)d_in[5];
    const float* bias   = (const float*)d_in[6];
    const float* W1     = (const float*)d_in[7];
    const float* b1     = (const float*)d_in[8];
    const float* W2     = (const float*)d_in[9];
    const float* b2     = (const float*)d_in[10];
    const float* araw   = (const float*)d_in[11];

    int n = in_sizes[1];   // number of keys (key_positions length)

    precompute_coef<<<(NBINS * NFREQ * NKERN + 255) / 256, 256>>>(mu, kappa, weight, ra);

    int grid = (n + KPB - 1) / KPB;
    key_pruning_main<<<grid, TPB>>>((const float2*)K, pos, bias, W1, b1, W2, b2, araw,
                                    (float*)d_out, n);
}